// round 2
// baseline (speedup 1.0000x reference)
#include <cuda_runtime.h>
#include <cuda_bf16.h>

// Problem shapes (fixed by dataset)
#define KK 2048   // batch/k dim
#define MM 512    // feature dim m
#define NN 64     // target dim n
#define EPSV 1e-8f

// ---------------- scratch (static device globals; no allocation) ----------------
__device__ float g_S[KK * MM];     // logits x @ w_att
__device__ float g_soft[KK * MM];  // softmax + eps
__device__ float g_hard[MM * NN];  // scores_hard

// ---------------- Kernel 1: fp32 tiled GEMM  S = x @ w_att ----------------
// C[KK, MM] = A[KK, 512] * B[512, MM]
#define BM 64
#define BN 64
#define BK 16
__global__ __launch_bounds__(256) void gemm_kernel(const float* __restrict__ A,
                                                   const float* __restrict__ B) {
    __shared__ float As[BK][BM + 4];  // transposed A tile, padded vs STS conflicts
    __shared__ float Bs[BK][BN];

    const int t  = threadIdx.x;
    const int tx = t & 15;        // 0..15
    const int ty = t >> 4;        // 0..15
    const int bm = blockIdx.y * BM;
    const int bn = blockIdx.x * BN;

    // A-load mapping: each thread loads one float4 of A, stores transposed
    const int arow = t >> 2;            // 0..63
    const int ac4  = (t & 3) << 2;      // 0,4,8,12
    // B-load mapping
    const int brow = t >> 4;            // 0..15
    const int bc4  = (t & 15) << 2;     // 0..60

    float acc[4][4];
#pragma unroll
    for (int i = 0; i < 4; i++)
#pragma unroll
        for (int j = 0; j < 4; j++) acc[i][j] = 0.f;

    for (int kt = 0; kt < MM; kt += BK) {
        float4 av = *(const float4*)&A[(size_t)(bm + arow) * MM + kt + ac4];
        As[ac4 + 0][arow] = av.x;
        As[ac4 + 1][arow] = av.y;
        As[ac4 + 2][arow] = av.z;
        As[ac4 + 3][arow] = av.w;
        *(float4*)&Bs[brow][bc4] =
            *(const float4*)&B[(size_t)(kt + brow) * MM + bn + bc4];
        __syncthreads();

#pragma unroll
        for (int kk = 0; kk < BK; kk++) {
            float4 a = *(const float4*)&As[kk][ty << 2];
            float4 b = *(const float4*)&Bs[kk][tx << 2];
            acc[0][0] += a.x * b.x; acc[0][1] += a.x * b.y; acc[0][2] += a.x * b.z; acc[0][3] += a.x * b.w;
            acc[1][0] += a.y * b.x; acc[1][1] += a.y * b.y; acc[1][2] += a.y * b.z; acc[1][3] += a.y * b.w;
            acc[2][0] += a.z * b.x; acc[2][1] += a.z * b.y; acc[2][2] += a.z * b.z; acc[2][3] += a.z * b.w;
            acc[3][0] += a.w * b.x; acc[3][1] += a.w * b.y; acc[3][2] += a.w * b.z; acc[3][3] += a.w * b.w;
        }
        __syncthreads();
    }

#pragma unroll
    for (int i = 0; i < 4; i++) {
        float4 v = make_float4(acc[i][0], acc[i][1], acc[i][2], acc[i][3]);
        *(float4*)&g_S[(size_t)(bm + (ty << 2) + i) * MM + bn + (tx << 2)] = v;
    }
}

// ---------------- Kernel 2: row softmax (+EPS) ----------------
// one block per k row, 256 threads, 2 elements per thread
__global__ __launch_bounds__(256) void softmax_kernel(float* __restrict__ out_soft) {
    const int k   = blockIdx.x;
    const int tid = threadIdx.x;
    const float* row = g_S + (size_t)k * MM;

    float v0 = row[tid];
    float v1 = row[tid + 256];

    __shared__ float red[256];
    red[tid] = fmaxf(v0, v1);
    __syncthreads();
#pragma unroll
    for (int s = 128; s > 0; s >>= 1) {
        if (tid < s) red[tid] = fmaxf(red[tid], red[tid + s]);
        __syncthreads();
    }
    float mx = red[0];
    __syncthreads();

    float e0 = expf(v0 - mx);
    float e1 = expf(v1 - mx);
    red[tid] = e0 + e1;
    __syncthreads();
#pragma unroll
    for (int s = 128; s > 0; s >>= 1) {
        if (tid < s) red[tid] += red[tid + s];
        __syncthreads();
    }
    float inv = 1.f / red[0];

    float s0 = e0 * inv + EPSV;
    float s1 = e1 * inv + EPSV;
    size_t base = (size_t)k * MM;
    g_soft[base + tid]       = s0;
    g_soft[base + tid + 256] = s1;
    if (out_soft) {
        out_soft[base + tid]       = s0;
        out_soft[base + tid + 256] = s1;
    }
}

// ---------------- Kernel 3: top-l threshold + scores_hard ----------------
// one block, 64 threads; thread n handles column n of w_b
__global__ __launch_bounds__(64) void hard_kernel(const float* __restrict__ wb,
                                                  const int* __restrict__ lptr,
                                                  float* __restrict__ out_hard) {
    const int n = threadIdx.x;
    if (n >= NN) return;
    int l = lptr ? *lptr : 8;
    if (l < 1) l = 1;
    if (l > 64) l = 64;

    float top[64];
    for (int i = 0; i < l; i++) top[i] = -3.4e38f;
    for (int m = 0; m < MM; m++) {
        float v = wb[m * NN + n];
        if (v > top[l - 1]) {
            int j = l - 1;
            while (j > 0 && top[j - 1] < v) {
                top[j] = top[j - 1];
                j--;
            }
            top[j] = v;
        }
    }
    float thr = top[l - 1];

    for (int m = 0; m < MM; m++) {
        float sh = wb[m * NN + n] - thr + EPSV;
        sh = fminf(fmaxf(sh, -1.f), 1.f);
        float h = (sh + 1.f) * 0.5f;
        g_hard[m * NN + n] = h;
        if (out_hard) out_hard[m * NN + n] = h;
    }
}

// ---------------- Kernel 4: epilogue — out & mask_weight ----------------
// 16 threads per (k,m); each owns one float4 of n. Warp writes 1KB contiguous.
__global__ __launch_bounds__(256) void epilogue_kernel(const float* __restrict__ x,
                                                       float* __restrict__ out,
                                                       float* __restrict__ mw) {
    const int idx = blockIdx.x * blockDim.x + threadIdx.x;  // 0 .. KK*MM*16-1
    const int n4  = idx & 15;
    const int km  = idx >> 4;       // 0 .. KK*MM-1
    const int m   = km & (MM - 1);

    float ss = g_soft[km];
    float xv = __ldg(&x[km]);
    float4 h = __ldg((const float4*)(g_hard + m * NN + (n4 << 2)));

    float4 mw4 = make_float4(h.x * ss, h.y * ss, h.z * ss, h.w * ss);
    float4 o4  = make_float4(mw4.x * xv, mw4.y * xv, mw4.z * xv, mw4.w * xv);

    size_t base = (size_t)km * NN + (n4 << 2);
    *(float4*)&out[base] = o4;
    if (mw) *(float4*)&mw[base] = mw4;
}

// ---------------- launch ----------------
extern "C" void kernel_launch(void* const* d_in, const int* in_sizes, int n_in,
                              void* d_out, int out_size) {
    const float* x     = (const float*)d_in[0];
    const float* w_att = (const float*)d_in[1];
    const float* w_b   = (const float*)d_in[2];
    const int*   lptr  = (n_in > 3) ? (const int*)d_in[3] : nullptr;

    const long SZ_OUT  = (long)KK * MM * NN;   // 67108864
    const long SZ_HARD = (long)MM * NN;        // 32768
    const long SZ_SOFT = (long)KK * MM;        // 1048576

    float* out_ptr  = (float*)d_out;
    float* hard_ptr = nullptr;
    float* soft_ptr = nullptr;
    float* mw_ptr   = nullptr;
    if ((long)out_size >= SZ_OUT + SZ_HARD + SZ_SOFT + SZ_OUT) {
        hard_ptr = out_ptr + SZ_OUT;
        soft_ptr = hard_ptr + SZ_HARD;
        mw_ptr   = soft_ptr + SZ_SOFT;
    }

    // GEMM: grid (MM/BN, KK/BM)
    dim3 ggrid(MM / BN, KK / BM);
    gemm_kernel<<<ggrid, 256>>>(x, w_att);

    // independent small kernel
    hard_kernel<<<1, 64>>>(w_b, lptr, hard_ptr);

    // softmax: one block per row
    softmax_kernel<<<KK, 256>>>(soft_ptr);

    // epilogue: KK*MM*16 threads
    int total = KK * MM * 16;
    epilogue_kernel<<<total / 256, 256>>>(x, out_ptr, mw_ptr);
}

// round 3
// speedup vs baseline: 2.6711x; 2.6711x over previous
#include <cuda_runtime.h>
#include <cuda_bf16.h>

// Problem shapes (fixed by dataset)
#define KK 2048   // batch/k dim
#define MM 512    // feature dim m
#define NN 64     // target dim n
#define EPSV 1e-8f
#define LMAX 32

// ---------------- scratch (static device globals; no allocation) ----------------
__device__ float g_S[KK * MM];     // logits x @ w_att
__device__ float g_soft[KK * MM];  // softmax + eps
__device__ float g_hard[MM * NN];  // scores_hard

// ---------------- Kernel 1: fp32 tiled GEMM  S = x @ w_att ----------------
#define BM 64
#define BN 64
#define BK 16
__global__ __launch_bounds__(256) void gemm_kernel(const float* __restrict__ A,
                                                   const float* __restrict__ B) {
    __shared__ float As[BK][BM + 4];
    __shared__ float Bs[BK][BN];

    const int t  = threadIdx.x;
    const int tx = t & 15;
    const int ty = t >> 4;
    const int bm = blockIdx.y * BM;
    const int bn = blockIdx.x * BN;

    const int arow = t >> 2;
    const int ac4  = (t & 3) << 2;
    const int brow = t >> 4;
    const int bc4  = (t & 15) << 2;

    float acc[4][4];
#pragma unroll
    for (int i = 0; i < 4; i++)
#pragma unroll
        for (int j = 0; j < 4; j++) acc[i][j] = 0.f;

    for (int kt = 0; kt < MM; kt += BK) {
        float4 av = *(const float4*)&A[(size_t)(bm + arow) * MM + kt + ac4];
        As[ac4 + 0][arow] = av.x;
        As[ac4 + 1][arow] = av.y;
        As[ac4 + 2][arow] = av.z;
        As[ac4 + 3][arow] = av.w;
        *(float4*)&Bs[brow][bc4] =
            *(const float4*)&B[(size_t)(kt + brow) * MM + bn + bc4];
        __syncthreads();

#pragma unroll
        for (int kk = 0; kk < BK; kk++) {
            float4 a = *(const float4*)&As[kk][ty << 2];
            float4 b = *(const float4*)&Bs[kk][tx << 2];
            acc[0][0] += a.x * b.x; acc[0][1] += a.x * b.y; acc[0][2] += a.x * b.z; acc[0][3] += a.x * b.w;
            acc[1][0] += a.y * b.x; acc[1][1] += a.y * b.y; acc[1][2] += a.y * b.z; acc[1][3] += a.y * b.w;
            acc[2][0] += a.z * b.x; acc[2][1] += a.z * b.y; acc[2][2] += a.z * b.z; acc[2][3] += a.z * b.w;
            acc[3][0] += a.w * b.x; acc[3][1] += a.w * b.y; acc[3][2] += a.w * b.z; acc[3][3] += a.w * b.w;
        }
        __syncthreads();
    }

#pragma unroll
    for (int i = 0; i < 4; i++) {
        float4 v = make_float4(acc[i][0], acc[i][1], acc[i][2], acc[i][3]);
        *(float4*)&g_S[(size_t)(bm + (ty << 2) + i) * MM + bn + (tx << 2)] = v;
    }
}

// ---------------- Kernel 2: row softmax (+EPS) ----------------
__global__ __launch_bounds__(256) void softmax_kernel(float* __restrict__ out_soft) {
    const int k   = blockIdx.x;
    const int tid = threadIdx.x;
    const float* row = g_S + (size_t)k * MM;

    float v0 = row[tid];
    float v1 = row[tid + 256];

    __shared__ float red[256];
    red[tid] = fmaxf(v0, v1);
    __syncthreads();
#pragma unroll
    for (int s = 128; s > 0; s >>= 1) {
        if (tid < s) red[tid] = fmaxf(red[tid], red[tid + s]);
        __syncthreads();
    }
    float mx = red[0];
    __syncthreads();

    float e0 = __expf(v0 - mx);
    float e1 = __expf(v1 - mx);
    red[tid] = e0 + e1;
    __syncthreads();
#pragma unroll
    for (int s = 128; s > 0; s >>= 1) {
        if (tid < s) red[tid] += red[tid + s];
        __syncthreads();
    }
    float inv = 1.f / red[0];

    float s0 = e0 * inv + EPSV;
    float s1 = e1 * inv + EPSV;
    size_t base = (size_t)k * MM;
    g_soft[base + tid]       = s0;
    g_soft[base + tid + 256] = s1;
    if (out_soft) {
        out_soft[base + tid]       = s0;
        out_soft[base + tid + 256] = s1;
    }
}

// ---------------- Kernel 3: per-column top-l threshold + hard scores ----------
// 64 blocks (one per n-column) x 32 threads. Lane holds 16 values of the
// column in registers; local insertion top-l; warp merge via l rounds of
// argmax-extract; then fused hard-score computation from the register copy.
__global__ __launch_bounds__(32) void hard_kernel(const float* __restrict__ wb,
                                                  const int* __restrict__ lptr,
                                                  float* __restrict__ out_hard) {
    const int n    = blockIdx.x;
    const int lane = threadIdx.x;
    int l = lptr ? *lptr : 8;
    if (l < 1) l = 1;
    if (l > LMAX) l = LMAX;

    // load this column: lane handles m = lane*16 .. lane*16+15
    float v[16];
#pragma unroll
    for (int i = 0; i < 16; i++)
        v[i] = wb[(lane * 16 + i) * NN + n];

    // local top-l (descending) via insertion
    float top[LMAX];
    for (int i = 0; i < l; i++) top[i] = -3.4e38f;
#pragma unroll
    for (int i = 0; i < 16; i++) {
        float x = v[i];
        if (x > top[l - 1]) {
            int j = l - 1;
            while (j > 0 && top[j - 1] < x) { top[j] = top[j - 1]; j--; }
            top[j] = x;
        }
    }

    // warp merge: l rounds of extract-max across lanes' sorted lists
    int ptr = 0;
    float thr = -3.4e38f;
    for (int r = 0; r < l; r++) {
        float cand = (ptr < l) ? top[ptr] : -3.4e38f;
        float m = cand;
#pragma unroll
        for (int off = 16; off > 0; off >>= 1)
            m = fmaxf(m, __shfl_xor_sync(0xffffffffu, m, off));
        unsigned b = __ballot_sync(0xffffffffu, cand == m);
        int src = __ffs(b) - 1;
        if (lane == src) ptr++;
        thr = m;
    }

    // hard scores from the register-resident column values
#pragma unroll
    for (int i = 0; i < 16; i++) {
        float sh = v[i] - thr + EPSV;
        sh = fminf(fmaxf(sh, -1.f), 1.f);
        float h = (sh + 1.f) * 0.5f;
        int m = lane * 16 + i;
        g_hard[m * NN + n] = h;
        if (out_hard) out_hard[m * NN + n] = h;
    }
}

// ---------------- Kernel 4: epilogue — out & mask_weight ----------------
// 8 threads per (k,m); each owns 8 n-values (2 x float4). Streaming stores.
__global__ __launch_bounds__(256) void epilogue_kernel(const float* __restrict__ x,
                                                       float* __restrict__ out,
                                                       float* __restrict__ mw) {
    const int idx = blockIdx.x * blockDim.x + threadIdx.x;  // 0 .. KK*MM*8-1
    const int n8  = (idx & 7) << 3;   // 0,8,...,56
    const int km  = idx >> 3;         // 0 .. KK*MM-1
    const int m   = km & (MM - 1);

    float ss = g_soft[km];
    float xv = __ldg(&x[km]);
    float4 h0 = __ldg((const float4*)(g_hard + m * NN + n8));
    float4 h1 = __ldg((const float4*)(g_hard + m * NN + n8 + 4));

    float4 mwa = make_float4(h0.x * ss, h0.y * ss, h0.z * ss, h0.w * ss);
    float4 mwb = make_float4(h1.x * ss, h1.y * ss, h1.z * ss, h1.w * ss);
    float4 oa  = make_float4(mwa.x * xv, mwa.y * xv, mwa.z * xv, mwa.w * xv);
    float4 ob  = make_float4(mwb.x * xv, mwb.y * xv, mwb.z * xv, mwb.w * xv);

    size_t base = (size_t)km * NN + n8;
    __stcs((float4*)&out[base],     oa);
    __stcs((float4*)&out[base + 4], ob);
    if (mw) {
        __stcs((float4*)&mw[base],     mwa);
        __stcs((float4*)&mw[base + 4], mwb);
    }
}

// ---------------- launch ----------------
extern "C" void kernel_launch(void* const* d_in, const int* in_sizes, int n_in,
                              void* d_out, int out_size) {
    const float* x     = (const float*)d_in[0];
    const float* w_att = (const float*)d_in[1];
    const float* w_b   = (const float*)d_in[2];
    const int*   lptr  = (n_in > 3) ? (const int*)d_in[3] : nullptr;

    const long SZ_OUT  = (long)KK * MM * NN;
    const long SZ_HARD = (long)MM * NN;
    const long SZ_SOFT = (long)KK * MM;

    float* out_ptr  = (float*)d_out;
    float* hard_ptr = nullptr;
    float* soft_ptr = nullptr;
    float* mw_ptr   = nullptr;
    if ((long)out_size >= SZ_OUT + SZ_HARD + SZ_SOFT + SZ_OUT) {
        hard_ptr = out_ptr + SZ_OUT;
        soft_ptr = hard_ptr + SZ_HARD;
        mw_ptr   = soft_ptr + SZ_SOFT;
    }

    dim3 ggrid(MM / BN, KK / BM);
    gemm_kernel<<<ggrid, 256>>>(x, w_att);

    hard_kernel<<<NN, 32>>>(w_b, lptr, hard_ptr);

    softmax_kernel<<<KK, 256>>>(soft_ptr);

    int total = KK * MM * 8;
    epilogue_kernel<<<total / 256, 256>>>(x, out_ptr, mw_ptr);
}